// round 9
// baseline (speedup 1.0000x reference)
#include <cuda_runtime.h>
#include <math.h>

#define NFRAMES   16384
#define HOPC      240
#define HOP2XC    480
#define L2X       (NFRAMES*HOP2XC)      /* 7,864,320 */
#define NSTFT     (NFRAMES+1)           /* 16385 */
#define OUTLEN    (NFRAMES*HOPC)        /* 3,932,160 */
#define PI_D      3.14159265358979323846

#define LEN48   (48*1024+1)
#define LEN144  (144*1024+1)
#define LEN432  (432*1024+1)

#define NCHUNK  128
#define CHUNKSZ 128   /* NCHUNK*CHUNKSZ == NFRAMES */

// ---------------- static device scratch ----------------
__device__ float  g_p2x[L2X];
__device__ float  g_ybuf[NSTFT * 512];
__device__ double g_S[NFRAMES];
__device__ double g_ex[NFRAMES];
__device__ double g_csum[NCHUNK];
__device__ double g_cbase[NCHUNK];
__device__ double g_c1[NFRAMES];
__device__ double g_c2h[NFRAMES];
__device__ float  g_c1f[NFRAMES];
__device__ float  g_c2hf[NFRAMES];
__device__ float  g_af[NFRAMES];
__device__ float  g_bf[NFRAMES];
__device__ unsigned char g_vuv[NFRAMES + 1];
__device__ float  g_w1024[1024];
__device__ float  g_w512[512];
__device__ float  g_ienv[240];
__device__ float2 g_tw[1024];                 // exp(-2*pi*i*k/1024)
__device__ float  g_trans[HOP2XC];
__device__ float2 g_pr48[LEN48];
__device__ float2 g_pr144[LEN144];
__device__ float2 g_pr432[LEN432];

// ---------------- helpers ----------------
__device__ __forceinline__ float2 cmul(float2 a, float2 b) {
    return make_float2(a.x * b.x - a.y * b.y, a.x * b.y + a.y * b.x);
}
__device__ __forceinline__ float2 cadd(float2 a, float2 b) { return make_float2(a.x + b.x, a.y + b.y); }
__device__ __forceinline__ float2 csub(float2 a, float2 b) { return make_float2(a.x - b.x, a.y - b.y); }
__device__ __forceinline__ float2 jmul(float2 a) { return make_float2(-a.y, a.x); }   // i*a

#define PADI(i) ((i) + ((i) >> 3))   /* pad every 8 float2 */
#define PADSZ   (512 + 64)

__device__ __forceinline__ float hannf512(int n) {
    return (float)(0.5 - 0.5 * cos(2.0 * PI_D * (double)n / 512.0));
}

// 128-thread (4-warp) inclusive scan of one double per thread
__device__ __forceinline__ double block128_incl_scan(double s, double* warpsum) {
    const int t = threadIdx.x;
    const int lane = t & 31;
    const int wid = t >> 5;
    double v = s;
    #pragma unroll
    for (int off = 1; off < 32; off <<= 1) {
        double n = __shfl_up_sync(0xffffffffu, v, off);
        if (lane >= off) v += n;
    }
    if (lane == 31) warpsum[wid] = v;
    __syncthreads();
    if (t == 0) {
        double acc = 0.0;
        #pragma unroll
        for (int w = 0; w < 4; w++) { double x = warpsum[w]; warpsum[w] = acc; acc += x; }
    }
    __syncthreads();
    return v + warpsum[wid];
}

// ---------------- K-init: fused setup + pair tables + per-frame values ----------------
__global__ void k_init(const float* __restrict__ f0,
                       const float* __restrict__ py48, const float* __restrict__ py144,
                       const float* __restrict__ py432) {
    int i = blockIdx.x * blockDim.x + threadIdx.x;
    if (i < LEN48)  g_pr48[i]  = make_float2(py48[i],  py48[min(i + 1, LEN48 - 1)]);
    if (i < LEN144) g_pr144[i] = make_float2(py144[i], py144[min(i + 1, LEN144 - 1)]);
    if (i < LEN432) g_pr432[i] = make_float2(py432[i], py432[min(i + 1, LEN432 - 1)]);
    if (i < 1024) {
        g_w1024[i] = (float)(0.5 - 0.5 * cos(2.0 * PI_D * (double)i / 1024.0));
        double ang = -2.0 * PI_D * (double)i / 1024.0;
        g_tw[i] = make_float2((float)cos(ang), (float)sin(ang));
        if (i < 512) g_w512[i] = hannf512(i);
        if (i < HOP2XC) {
            double s = sin(((double)i / (double)HOP2XC) * (PI_D * 0.5));
            g_trans[i] = (float)(s * s);
        }
        if (i < 240) {
            float w0 = hannf512(i), w1 = hannf512(i + 240);
            float env = ((i <= 31) ? hannf512(i + 480) * hannf512(i + 480) : 0.0f)
                        + w1 * w1 + w0 * w0;
            g_ienv[i] = 1.0f / env;
        }
    }
    if (i < NFRAMES) {
        double fi = (double)f0[i];
        double fn = (i + 1 < NFRAMES) ? (double)f0[i + 1] : 0.0;
        double a = (fi != 0.0) ? fi : fn;
        double b = (fn != 0.0) ? fn : fi;
        g_af[i] = (float)a;
        g_bf[i] = (float)b;
        double c1 = a / 96000.0;
        double c2h = (b - a) / (2.0 * 480.0 * 96000.0);
        g_c1[i] = c1;
        g_c2h[i] = c2h;
        g_c1f[i] = (float)c1;
        g_c2hf[i] = (float)c2h;
        g_S[i] = (480.0 * a + (b - a) * (114960.0 / 480.0)) / 96000.0;
        unsigned char m = 0;
        if (fi >= 500.0 && fi < 1500.0) m |= 1;
        if (fi >= (24000.0 / 144.0) && fi < 500.0) m |= 2;
        if (fi >= (24000.0 / 432.0) && fi < (24000.0 / 144.0)) m |= 4;
        g_vuv[i] = m;
        if (i == NFRAMES - 1) g_vuv[NFRAMES] = 0;
    }
}

// ---------------- K2a/b: distributed frame scan ----------------
__global__ void __launch_bounds__(CHUNKSZ) k_scan1() {
    __shared__ double warpsum[4];
    const int i = blockIdx.x * CHUNKSZ + threadIdx.x;
    const double s = g_S[i];
    const double v = block128_incl_scan(s, warpsum);
    g_ex[i] = v - s;
    if (threadIdx.x == CHUNKSZ - 1) g_csum[blockIdx.x] = v;
}

__global__ void __launch_bounds__(NCHUNK) k_scan2() {
    __shared__ double warpsum[4];
    const double s = g_csum[threadIdx.x];
    const double v = block128_incl_scan(s, warpsum);
    g_cbase[threadIdx.x] = v - s;
}

// ---------------- K3: excitation; fp64 only for the thread's first sample ----------------
__device__ __forceinline__ float band_lookup(const float2* __restrict__ pair, int maxi,
                                             float phase, float tr, float v0, float v1) {
    if (v0 == 0.0f && v1 == 0.0f) return 0.0f;
    float mask = v0 + (v1 - v0) * tr;
    float idxf = phase * (float)maxi;
    idxf = fminf(fmaxf(idxf, 0.0f), (float)maxi);
    int lo = (int)floorf(idxf);
    float tt = idxf - (float)lo;
    float2 p = __ldg(pair + lo);
    return mask * (p.x + (p.y - p.x) * tt);
}

__global__ void __launch_bounds__(256) k_gen() {
    const int t = blockIdx.x * blockDim.x + threadIdx.x;
    const int s0 = t * 4;
    const int i = s0 / 480;
    const int j0 = s0 - i * 480;

    // u0 in fp64 (exact match to reference cumsum chain)
    const double base0 = g_cbase[i >> 7] + g_ex[i];
    const double u0 = base0 + (double)(j0 + 1) * g_c1[i]
                      + (double)(j0 * (j0 + 1)) * g_c2h[i];
    const float ph0 = (float)(u0 - floor(u0));

    const float c1f = g_c1f[i], c2hf = g_c2hf[i];
    const float af = g_af[i], bf = g_bf[i];
    const unsigned vi = g_vuv[i], vn = g_vuv[i + 1];
    const float v48a = (float)(vi & 1),         v48b = (float)(vn & 1);
    const float v144a = (float)((vi >> 1) & 1), v144b = (float)((vn >> 1) & 1);
    const float v432a = (float)((vi >> 2) & 1), v432b = (float)((vn >> 2) & 1);

    float ph[4], trv[4], f0cv[4];
    ph[0] = ph0;
    #pragma unroll
    for (int r = 1; r < 4; r++) {
        // delta_r = u(j0+r) - u(j0) = r*c1 + r*(2*j0+r+1)*c2h  (small, f32-safe)
        const float delta = (float)r * c1f + (float)(r * (2 * j0 + r + 1)) * c2hf;
        const float p = ph0 + delta;
        ph[r] = p - floorf(p);
    }
    #pragma unroll
    for (int r = 0; r < 4; r++) {
        trv[r] = g_trans[j0 + r];
        f0cv[r] = af + (bf - af) * ((float)(j0 + r) * (1.0f / 480.0f));
    }

    float4 out;
    float* op = (float*)&out;
    #pragma unroll
    for (int r = 0; r < 4; r++) {
        float acc = 0.0f;
        acc += band_lookup(g_pr48, 48 * 1024, ph[r], trv[r], v48a, v48b);
        acc += band_lookup(g_pr144, 144 * 1024, ph[r], trv[r], v144a, v144b);
        acc += band_lookup(g_pr432, 432 * 1024, ph[r], trv[r], v432a, v432b);
        op[r] = acc * f0cv[r] * (1.0f / 48000.0f);
    }
    *(float4*)(g_p2x + s0) = out;
}

// ---------------- K4: STFT->truncate->ISTFT via FFT512 + packed IFFT256 ----------------
template<int N, int S>
__device__ __forceinline__ void step8(const float2* __restrict__ src, float2* __restrict__ dst,
                                      int t) {
    constexpr int N1 = N / 8;
    constexpr int M = 1024 / N;
    const int p = t / S;
    const int q = t - p * S;

    float2 x[8];
    #pragma unroll
    for (int r = 0; r < 8; r++) x[r] = src[PADI(q + S * (p + r * N1))];

    float2 ea = cadd(x[0], x[4]), eb = csub(x[0], x[4]);
    float2 ec = cadd(x[2], x[6]), ed = csub(x[2], x[6]);
    float2 E0 = cadd(ea, ec), E2 = csub(ea, ec);
    float2 E1 = csub(eb, jmul(ed)), E3 = cadd(eb, jmul(ed));

    float2 oa = cadd(x[1], x[5]), ob = csub(x[1], x[5]);
    float2 oc = cadd(x[3], x[7]), od = csub(x[3], x[7]);
    float2 O0 = cadd(oa, oc), O2 = csub(oa, oc);
    float2 O1 = csub(ob, jmul(od)), O3 = cadd(ob, jmul(od));

    const float C = 0.70710678118654752440f;
    float2 T1 = make_float2(C * (O1.x + O1.y), C * (O1.y - O1.x));
    float2 T2 = make_float2(O2.y, -O2.x);
    float2 T3 = make_float2(C * (O3.y - O3.x), -C * (O3.x + O3.y));

    float2 Y[8];
    Y[0] = cadd(E0, O0); Y[4] = csub(E0, O0);
    Y[1] = cadd(E1, T1); Y[5] = csub(E1, T1);
    Y[2] = cadd(E2, T2); Y[6] = csub(E2, T2);
    Y[3] = cadd(E3, T3); Y[7] = csub(E3, T3);

    if (N == 8) {
        #pragma unroll
        for (int r = 0; r < 8; r++) dst[PADI(q + S * (8 * p + r))] = Y[r];
    } else {
        const float2 w1 = __ldg(&g_tw[p * M]);
        const float2 w2 = cmul(w1, w1);
        const float2 w3 = cmul(w2, w1);
        const float2 w4 = cmul(w2, w2);
        const float2 w5 = cmul(w4, w1);
        const float2 w6 = cmul(w4, w2);
        const float2 w7 = cmul(w4, w3);
        dst[PADI(q + S * (8 * p + 0))] = Y[0];
        dst[PADI(q + S * (8 * p + 1))] = cmul(w1, Y[1]);
        dst[PADI(q + S * (8 * p + 2))] = cmul(w2, Y[2]);
        dst[PADI(q + S * (8 * p + 3))] = cmul(w3, Y[3]);
        dst[PADI(q + S * (8 * p + 4))] = cmul(w4, Y[4]);
        dst[PADI(q + S * (8 * p + 5))] = cmul(w5, Y[5]);
        dst[PADI(q + S * (8 * p + 6))] = cmul(w6, Y[6]);
        dst[PADI(q + S * (8 * p + 7))] = cmul(w7, Y[7]);
    }
}

template<int N, int S>
__device__ __forceinline__ void step4(const float2* __restrict__ src, float2* __restrict__ dst,
                                      int t) {
    constexpr int N1 = N / 4;
    constexpr int M = 1024 / N;
    const int p = t / S;
    const int q = t - p * S;
    float2 a = src[PADI(q + S * p)];
    float2 b = src[PADI(q + S * (p + N1))];
    float2 c = src[PADI(q + S * (p + 2 * N1))];
    float2 d = src[PADI(q + S * (p + 3 * N1))];
    float2 apc = cadd(a, c), amc = csub(a, c);
    float2 bpd = cadd(b, d), jbmd = jmul(csub(b, d));
    float2 Y0 = cadd(apc, bpd);
    float2 Y1 = csub(amc, jbmd);
    float2 Y2 = csub(apc, bpd);
    float2 Y3 = cadd(amc, jbmd);
    if (N == 4) {
        dst[PADI(q + S * (4 * p + 0))] = Y0;
        dst[PADI(q + S * (4 * p + 1))] = Y1;
        dst[PADI(q + S * (4 * p + 2))] = Y2;
        dst[PADI(q + S * (4 * p + 3))] = Y3;
    } else {
        const float2 w1 = __ldg(&g_tw[p * M]);
        const float2 w2 = cmul(w1, w1);
        const float2 w3 = cmul(w2, w1);
        dst[PADI(q + S * (4 * p + 0))] = Y0;
        dst[PADI(q + S * (4 * p + 1))] = cmul(w1, Y1);
        dst[PADI(q + S * (4 * p + 2))] = cmul(w2, Y2);
        dst[PADI(q + S * (4 * p + 3))] = cmul(w3, Y3);
    }
}

#define FPB 4   /* frames per block */

__global__ void __launch_bounds__(64 * FPB) k_fft() {
    __shared__ float2 Ub[FPB][PADSZ];
    __shared__ float2 Vb[FPB][PADSZ];
    const int tid = threadIdx.x;
    const int sub = tid >> 6;
    const int t = tid & 63;
    const int frame = blockIdx.x * FPB + sub;
    const bool valid = (frame < NSTFT);

    float2* U = Ub[sub];
    float2* V = Vb[sub];

    #pragma unroll
    for (int n0 = t; n0 < 512; n0 += 64) {
        float xe = 0.0f, xo = 0.0f;
        if (valid) {
            int ge = frame * HOP2XC - 512 + 2 * n0;
            if (ge >= 0 && ge + 1 < L2X) {
                float2 v = *(const float2*)(g_p2x + ge);
                xe = v.x; xo = v.y;
            } else {
                int go = ge + 1;
                if (ge < 0) ge = -ge;
                if (ge >= L2X) ge = 2 * L2X - 2 - ge;
                if (go < 0) go = -go;
                if (go >= L2X) go = 2 * L2X - 2 - go;
                xe = g_p2x[ge];
                xo = g_p2x[go];
            }
            xe *= g_w1024[2 * n0];
            xo *= g_w1024[2 * n0 + 1];
        }
        U[PADI(n0)] = make_float2(xe, xo);
    }
    __syncthreads();

    step8<512, 1>(U, V, t);  __syncthreads();
    step8<64, 8>(V, U, t);   __syncthreads();
    step8<8, 64>(U, V, t);   __syncthreads();

    for (int j = t; j <= 128; j += 64) {
        const float2 Zj = V[PADI(j)];
        const float2 Zmj = V[PADI((512 - j) & 511)];
        float2 E = make_float2(0.5f * (Zj.x + Zmj.x), 0.5f * (Zj.y - Zmj.y));
        float2 O = make_float2(0.5f * (Zj.y + Zmj.y), -0.5f * (Zj.x - Zmj.x));
        float2 Xa = cadd(E, cmul(__ldg(&g_tw[j]), O));
        if (j == 0) {
            const float X0r = Xa.x;
            const float X256r = V[PADI(256)].x;
            U[PADI(0)] = make_float2(0.5f * (X0r + X256r), -0.5f * (X0r - X256r));
        } else {
            const int jp = 256 - j;
            const float2 Zk = V[PADI(jp)];
            const float2 Zmk = V[PADI(256 + j)];
            float2 E2 = make_float2(0.5f * (Zk.x + Zmk.x), 0.5f * (Zk.y - Zmk.y));
            float2 O2 = make_float2(0.5f * (Zk.y + Zmk.y), -0.5f * (Zk.x - Zmk.x));
            float2 Xb = cadd(E2, cmul(__ldg(&g_tw[jp]), O2));

            const float2 t2 = __ldg(&g_tw[2 * j]);
            const float2 tp = make_float2(t2.x, -t2.y);
            const float2 tpn = make_float2(-t2.x, -t2.y);

            float2 S1 = make_float2(Xa.x + Xb.x, Xa.y - Xb.y);
            float2 D1 = make_float2(Xa.x - Xb.x, Xa.y + Xb.y);
            float2 zt = jmul(cmul(tp, D1));
            float2 zj = make_float2(0.5f * (S1.x + zt.x), 0.5f * (S1.y + zt.y));
            U[PADI(j)] = make_float2(zj.x, -zj.y);

            float2 S2 = make_float2(Xb.x + Xa.x, Xb.y - Xa.y);
            float2 D2 = make_float2(Xb.x - Xa.x, Xb.y + Xa.y);
            float2 zt2 = jmul(cmul(tpn, D2));
            float2 zp = make_float2(0.5f * (S2.x + zt2.x), 0.5f * (S2.y + zt2.y));
            U[PADI(jp)] = make_float2(zp.x, -zp.y);
        }
    }
    __syncthreads();

    step4<256, 1>(U, V, t);  __syncthreads();
    step4<64, 4>(V, U, t);   __syncthreads();
    step4<16, 16>(U, V, t);  __syncthreads();
    step4<4, 64>(V, U, t);   __syncthreads();

    if (valid) {
        #pragma unroll
        for (int m = t; m < 256; m += 64) {
            const float2 c = U[PADI(m)];
            float2 o;
            o.x = c.x * (1.0f / 256.0f) * g_w512[2 * m];
            o.y = -c.y * (1.0f / 256.0f) * g_w512[2 * m + 1];
            *(float2*)(g_ybuf + frame * 512 + 2 * m) = o;
        }
    }
}

// ---------------- K5: OLA, 2 samples/thread ----------------
__device__ __forceinline__ float ola_generic(int s) {
    int tlo = (s >= 512) ? (s - 511 + 239) / 240 : 0;
    int thi = s / 240;
    if (thi > NFRAMES) thi = NFRAMES;
    float sig = 0.0f, env = 0.0f;
    for (int t = tlo; t <= thi; t++) {
        const int m = s - 240 * t;
        const float w = g_w512[m];
        sig += g_ybuf[t * 512 + m];
        env += w * w;
    }
    return (env > 1e-11f) ? (sig / env) : 0.0f;
}

__global__ void __launch_bounds__(256) k_ola(float* __restrict__ out) {
    const int idx = blockIdx.x * blockDim.x + threadIdx.x;
    const int n0 = idx * 2;
    if (n0 >= OUTLEN) return;
    const int s = n0 + 256;

    if (s >= 512 && s <= 3932158) {
        const int thi = s / 240;
        const int r0 = s - 240 * thi;
        const float2 v0 = *(const float2*)(g_ybuf + thi * 512 + r0);
        const float2 v1 = *(const float2*)(g_ybuf + (thi - 1) * 512 + r0 + 240);
        float sig1 = v0.x + v1.x;
        float sig2 = v0.y + v1.y;
        if (r0 <= 30) {
            const float2 v2 = *(const float2*)(g_ybuf + (thi - 2) * 512 + r0 + 480);
            sig1 += v2.x;
            sig2 += v2.y;
        }
        float2 o;
        o.x = sig1 * g_ienv[r0];
        o.y = sig2 * g_ienv[r0 + 1];
        *(float2*)(out + n0) = o;
    } else {
        out[n0] = ola_generic(s);
        if (n0 + 1 < OUTLEN) out[n0 + 1] = ola_generic(s + 1);
    }
}

// ---------------- launcher ----------------
extern "C" void kernel_launch(void* const* d_in, const int* in_sizes, int n_in,
                              void* d_out, int out_size) {
    const float* f0    = (const float*)d_in[0];
    const float* py48  = (const float*)d_in[1];
    const float* py144 = (const float*)d_in[2];
    const float* py432 = (const float*)d_in[3];
    float* out = (float*)d_out;
    (void)in_sizes; (void)n_in; (void)out_size;

    k_init<<<(LEN432 + 255) / 256, 256>>>(f0, py48, py144, py432);
    k_scan1<<<NCHUNK, CHUNKSZ>>>();
    k_scan2<<<1, NCHUNK>>>();
    k_gen<<<L2X / 4 / 256, 256>>>();
    k_fft<<<(NSTFT + FPB - 1) / FPB, 64 * FPB>>>();
    k_ola<<<(OUTLEN / 2 + 255) / 256, 256>>>(out);
}

// round 11
// speedup vs baseline: 1.0686x; 1.0686x over previous
#include <cuda_runtime.h>
#include <math.h>

#define NFRAMES   16384
#define HOPC      240
#define HOP2XC    480
#define L2X       (NFRAMES*HOP2XC)      /* 7,864,320 */
#define NSTFT     (NFRAMES+1)           /* 16385 */
#define OUTLEN    (NFRAMES*HOPC)        /* 3,932,160 */
#define PI_D      3.14159265358979323846

#define LEN48   (48*1024+1)
#define LEN144  (144*1024+1)
#define LEN432  (432*1024+1)

#define NCHUNK  128
#define CHUNKSZ 128

// ---------------- static device scratch ----------------
__device__ float  g_p2x[L2X];
__device__ float  g_ybuf[NSTFT * 512];
__device__ double g_S[NFRAMES];
__device__ double g_ex[NFRAMES];
__device__ double g_csum[NCHUNK];
__device__ double g_cbase[NCHUNK];
__device__ double g_c1[NFRAMES];
__device__ double g_c2h[NFRAMES];
__device__ float  g_af[NFRAMES];
__device__ float  g_bf[NFRAMES];
__device__ unsigned char g_vuv[NFRAMES + 1];
__device__ float  g_w1024[1024];
__device__ float  g_w512[512];
__device__ float  g_ienv[240];
__device__ float2 g_tw[1024];                 // exp(-2*pi*i*k/1024)
__device__ float  g_trans[HOP2XC];
__device__ float2 g_pr48[LEN48];
__device__ float2 g_pr144[LEN144];
__device__ float2 g_pr432[LEN432];

// ---------------- helpers ----------------
__device__ __forceinline__ float2 cmul(float2 a, float2 b) {
    return make_float2(a.x * b.x - a.y * b.y, a.x * b.y + a.y * b.x);
}
__device__ __forceinline__ float2 cadd(float2 a, float2 b) { return make_float2(a.x + b.x, a.y + b.y); }
__device__ __forceinline__ float2 csub(float2 a, float2 b) { return make_float2(a.x - b.x, a.y - b.y); }
__device__ __forceinline__ float2 jmul(float2 a) { return make_float2(-a.y, a.x); }   // i*a

#define PADI(i) ((i) + ((i) >> 3))
#define PADSZ   (512 + 64)

__device__ __forceinline__ float hannf512(int n) {
    return (float)(0.5 - 0.5 * cos(2.0 * PI_D * (double)n / 512.0));
}

__device__ __forceinline__ double block128_incl_scan(double s, double* warpsum) {
    const int t = threadIdx.x;
    const int lane = t & 31;
    const int wid = t >> 5;
    double v = s;
    #pragma unroll
    for (int off = 1; off < 32; off <<= 1) {
        double n = __shfl_up_sync(0xffffffffu, v, off);
        if (lane >= off) v += n;
    }
    if (lane == 31) warpsum[wid] = v;
    __syncthreads();
    if (t == 0) {
        double acc = 0.0;
        #pragma unroll
        for (int w = 0; w < 4; w++) { double x = warpsum[w]; warpsum[w] = acc; acc += x; }
    }
    __syncthreads();
    return v + warpsum[wid];
}

// ---------------- K-init ----------------
__global__ void k_init(const float* __restrict__ f0,
                       const float* __restrict__ py48, const float* __restrict__ py144,
                       const float* __restrict__ py432) {
    int i = blockIdx.x * blockDim.x + threadIdx.x;
    if (i < LEN48)  g_pr48[i]  = make_float2(py48[i],  py48[min(i + 1, LEN48 - 1)]);
    if (i < LEN144) g_pr144[i] = make_float2(py144[i], py144[min(i + 1, LEN144 - 1)]);
    if (i < LEN432) g_pr432[i] = make_float2(py432[i], py432[min(i + 1, LEN432 - 1)]);
    if (i < 1024) {
        g_w1024[i] = (float)(0.5 - 0.5 * cos(2.0 * PI_D * (double)i / 1024.0));
        double ang = -2.0 * PI_D * (double)i / 1024.0;
        g_tw[i] = make_float2((float)cos(ang), (float)sin(ang));
        if (i < 512) g_w512[i] = hannf512(i);
        if (i < HOP2XC) {
            double s = sin(((double)i / (double)HOP2XC) * (PI_D * 0.5));
            g_trans[i] = (float)(s * s);
        }
        if (i < 240) {
            float w0 = hannf512(i), w1 = hannf512(i + 240);
            float env = ((i <= 31) ? hannf512(i + 480) * hannf512(i + 480) : 0.0f)
                        + w1 * w1 + w0 * w0;
            g_ienv[i] = 1.0f / env;
        }
    }
    if (i < NFRAMES) {
        double fi = (double)f0[i];
        double fn = (i + 1 < NFRAMES) ? (double)f0[i + 1] : 0.0;
        double a = (fi != 0.0) ? fi : fn;
        double b = (fn != 0.0) ? fn : fi;
        g_af[i] = (float)a;
        g_bf[i] = (float)b;
        g_c1[i] = a / 96000.0;
        g_c2h[i] = (b - a) / (2.0 * 480.0 * 96000.0);
        g_S[i] = (480.0 * a + (b - a) * (114960.0 / 480.0)) / 96000.0;
        unsigned char m = 0;
        if (fi >= 500.0 && fi < 1500.0) m |= 1;
        if (fi >= (24000.0 / 144.0) && fi < 500.0) m |= 2;
        if (fi >= (24000.0 / 432.0) && fi < (24000.0 / 144.0)) m |= 4;
        g_vuv[i] = m;
        if (i == NFRAMES - 1) g_vuv[NFRAMES] = 0;
    }
}

// ---------------- K2a/b: distributed frame scan ----------------
__global__ void __launch_bounds__(CHUNKSZ) k_scan1() {
    __shared__ double warpsum[4];
    const int i = blockIdx.x * CHUNKSZ + threadIdx.x;
    const double s = g_S[i];
    const double v = block128_incl_scan(s, warpsum);
    g_ex[i] = v - s;
    if (threadIdx.x == CHUNKSZ - 1) g_csum[blockIdx.x] = v;
}

__global__ void __launch_bounds__(NCHUNK) k_scan2() {
    __shared__ double warpsum[4];
    const double s = g_csum[threadIdx.x];
    const double v = block128_incl_scan(s, warpsum);
    g_cbase[threadIdx.x] = v - s;
}

// ---------------- K3: excitation (full fp64 phase; L1tex-bound, DP is free) ----------
__device__ __forceinline__ float band_lookup(const float2* __restrict__ pair, int maxi,
                                             float phase, float tr, float v0, float v1) {
    if (v0 == 0.0f && v1 == 0.0f) return 0.0f;
    float mask = v0 + (v1 - v0) * tr;
    float idxf = phase * (float)maxi;
    idxf = fminf(fmaxf(idxf, 0.0f), (float)maxi);
    int lo = (int)floorf(idxf);
    float tt = idxf - (float)lo;
    float2 p = __ldg(pair + lo);
    return mask * (p.x + (p.y - p.x) * tt);
}

__global__ void __launch_bounds__(256) k_gen() {
    const int t = blockIdx.x * blockDim.x + threadIdx.x;
    const int s0 = t * 4;
    const int i = s0 / 480;
    const int j0 = s0 - i * 480;

    const double base0 = g_cbase[i >> 7] + g_ex[i];
    const double base = base0 - floor(base0);
    const double c1 = g_c1[i], c2h = g_c2h[i];
    const float af = g_af[i], bf = g_bf[i];
    const unsigned vi = g_vuv[i], vn = g_vuv[i + 1];
    const float v48a = (float)(vi & 1),         v48b = (float)(vn & 1);
    const float v144a = (float)((vi >> 1) & 1), v144b = (float)((vn >> 1) & 1);
    const float v432a = (float)((vi >> 2) & 1), v432b = (float)((vn >> 2) & 1);

    float ph[4], trv[4], f0cv[4];
    #pragma unroll
    for (int r = 0; r < 4; r++) {
        const double jd = (double)(j0 + r);
        const double u = base + (jd + 1.0) * c1 + (jd * (jd + 1.0)) * c2h;
        ph[r] = (float)(u - floor(u));
        trv[r] = g_trans[j0 + r];
        f0cv[r] = af + (bf - af) * ((float)(j0 + r) * (1.0f / 480.0f));
    }

    float4 out;
    float* op = (float*)&out;
    #pragma unroll
    for (int r = 0; r < 4; r++) {
        float acc = 0.0f;
        acc += band_lookup(g_pr48, 48 * 1024, ph[r], trv[r], v48a, v48b);
        acc += band_lookup(g_pr144, 144 * 1024, ph[r], trv[r], v144a, v144b);
        acc += band_lookup(g_pr432, 432 * 1024, ph[r], trv[r], v432a, v432b);
        op[r] = acc * f0cv[r] * (1.0f / 48000.0f);
    }
    *(float4*)(g_p2x + s0) = out;
}

// ---------------- K4: fused-load FFT512 + packed IFFT256 with fused store ------------
__device__ __forceinline__ void dft8(const float2 x[8], float2 Y[8]) {
    float2 ea = cadd(x[0], x[4]), eb = csub(x[0], x[4]);
    float2 ec = cadd(x[2], x[6]), ed = csub(x[2], x[6]);
    float2 E0 = cadd(ea, ec), E2 = csub(ea, ec);
    float2 E1 = csub(eb, jmul(ed)), E3 = cadd(eb, jmul(ed));

    float2 oa = cadd(x[1], x[5]), ob = csub(x[1], x[5]);
    float2 oc = cadd(x[3], x[7]), od = csub(x[3], x[7]);
    float2 O0 = cadd(oa, oc), O2 = csub(oa, oc);
    float2 O1 = csub(ob, jmul(od)), O3 = cadd(ob, jmul(od));

    const float C = 0.70710678118654752440f;
    float2 T1 = make_float2(C * (O1.x + O1.y), C * (O1.y - O1.x));
    float2 T2 = make_float2(O2.y, -O2.x);
    float2 T3 = make_float2(C * (O3.y - O3.x), -C * (O3.x + O3.y));

    Y[0] = cadd(E0, O0); Y[4] = csub(E0, O0);
    Y[1] = cadd(E1, T1); Y[5] = csub(E1, T1);
    Y[2] = cadd(E2, T2); Y[6] = csub(E2, T2);
    Y[3] = cadd(E3, T3); Y[7] = csub(E3, T3);
}

__device__ __forceinline__ void twiddle_store8(float2* __restrict__ dst, const float2 Y[8],
                                               int p, int q, int S, int M) {
    if (p == 0) {
        #pragma unroll
        for (int r = 0; r < 8; r++) dst[PADI(q + S * r)] = Y[r];
    } else {
        const float2 w1 = __ldg(&g_tw[p * M]);
        const float2 w2 = cmul(w1, w1);
        const float2 w3 = cmul(w2, w1);
        const float2 w4 = cmul(w2, w2);
        const float2 w5 = cmul(w4, w1);
        const float2 w6 = cmul(w4, w2);
        const float2 w7 = cmul(w4, w3);
        dst[PADI(q + S * (8 * p + 0))] = Y[0];
        dst[PADI(q + S * (8 * p + 1))] = cmul(w1, Y[1]);
        dst[PADI(q + S * (8 * p + 2))] = cmul(w2, Y[2]);
        dst[PADI(q + S * (8 * p + 3))] = cmul(w3, Y[3]);
        dst[PADI(q + S * (8 * p + 4))] = cmul(w4, Y[4]);
        dst[PADI(q + S * (8 * p + 5))] = cmul(w5, Y[5]);
        dst[PADI(q + S * (8 * p + 6))] = cmul(w6, Y[6]);
        dst[PADI(q + S * (8 * p + 7))] = cmul(w7, Y[7]);
    }
}

template<int N, int S>
__device__ __forceinline__ void step8(const float2* __restrict__ src, float2* __restrict__ dst,
                                      int t) {
    constexpr int N1 = N / 8;
    constexpr int M = 1024 / N;
    const int p = t / S;
    const int q = t - p * S;
    float2 x[8], Y[8];
    #pragma unroll
    for (int r = 0; r < 8; r++) x[r] = src[PADI(q + S * (p + r * N1))];
    dft8(x, Y);
    twiddle_store8(dst, Y, p, q, S, M);
}

template<int N, int S>
__device__ __forceinline__ void step4(const float2* __restrict__ src, float2* __restrict__ dst,
                                      int t) {
    constexpr int N1 = N / 4;
    constexpr int M = 1024 / N;
    const int p = t / S;
    const int q = t - p * S;
    float2 a = src[PADI(q + S * p)];
    float2 b = src[PADI(q + S * (p + N1))];
    float2 c = src[PADI(q + S * (p + 2 * N1))];
    float2 d = src[PADI(q + S * (p + 3 * N1))];
    float2 apc = cadd(a, c), amc = csub(a, c);
    float2 bpd = cadd(b, d), jbmd = jmul(csub(b, d));
    float2 Y0 = cadd(apc, bpd);
    float2 Y1 = csub(amc, jbmd);
    float2 Y2 = csub(apc, bpd);
    float2 Y3 = cadd(amc, jbmd);
    const float2 w1 = __ldg(&g_tw[p * M]);
    const float2 w2 = cmul(w1, w1);
    const float2 w3 = cmul(w2, w1);
    dst[PADI(q + S * (4 * p + 0))] = Y0;
    dst[PADI(q + S * (4 * p + 1))] = cmul(w1, Y1);
    dst[PADI(q + S * (4 * p + 2))] = cmul(w2, Y2);
    dst[PADI(q + S * (4 * p + 3))] = cmul(w3, Y3);
}

#define FPB 4

__global__ void __launch_bounds__(64 * FPB) k_fft() {
    __shared__ float2 Ub[FPB][PADSZ];
    __shared__ float2 Vb[FPB][PADSZ];
    const int tid = threadIdx.x;
    const int sub = tid >> 6;
    const int t = tid & 63;
    const int frame = blockIdx.x * FPB + sub;
    const bool valid = (frame < NSTFT);

    float2* U = Ub[sub];
    float2* V = Vb[sub];

    // ---- fused: gmem load + window + pack + first radix-8 stage (S=1, p=t, q=0) ----
    {
        float2 x[8], Y[8];
        #pragma unroll
        for (int r = 0; r < 8; r++) {
            const int n0 = t + 64 * r;
            float xe = 0.0f, xo = 0.0f;
            if (valid) {
                int ge = frame * HOP2XC - 512 + 2 * n0;
                if (ge >= 0 && ge + 1 < L2X) {
                    float2 v = *(const float2*)(g_p2x + ge);
                    xe = v.x; xo = v.y;
                } else {
                    int go = ge + 1;
                    if (ge < 0) ge = -ge;
                    if (ge >= L2X) ge = 2 * L2X - 2 - ge;
                    if (go < 0) go = -go;
                    if (go >= L2X) go = 2 * L2X - 2 - go;
                    xe = g_p2x[ge];
                    xo = g_p2x[go];
                }
                xe *= g_w1024[2 * n0];
                xo *= g_w1024[2 * n0 + 1];
            }
            x[r] = make_float2(xe, xo);
        }
        dft8(x, Y);
        twiddle_store8(V, Y, t, 0, 1, 2);     // N=512: S=1, M=2
    }
    __syncthreads();

    step8<64, 8>(V, U, t);   __syncthreads();
    step8<8, 64>(U, V, t);   __syncthreads();

    // unpack real-FFT bins X[0..256], build conj of irfft-256 packing in U[0..255]
    for (int j = t; j <= 128; j += 64) {
        const float2 Zj = V[PADI(j)];
        const float2 Zmj = V[PADI((512 - j) & 511)];
        float2 E = make_float2(0.5f * (Zj.x + Zmj.x), 0.5f * (Zj.y - Zmj.y));
        float2 O = make_float2(0.5f * (Zj.y + Zmj.y), -0.5f * (Zj.x - Zmj.x));
        float2 Xa = cadd(E, cmul(__ldg(&g_tw[j]), O));
        if (j == 0) {
            const float X0r = Xa.x;
            const float X256r = V[PADI(256)].x;
            U[PADI(0)] = make_float2(0.5f * (X0r + X256r), -0.5f * (X0r - X256r));
        } else {
            const int jp = 256 - j;
            const float2 Zk = V[PADI(jp)];
            const float2 Zmk = V[PADI(256 + j)];
            float2 E2 = make_float2(0.5f * (Zk.x + Zmk.x), 0.5f * (Zk.y - Zmk.y));
            float2 O2 = make_float2(0.5f * (Zk.y + Zmk.y), -0.5f * (Zk.x - Zmk.x));
            float2 Xb = cadd(E2, cmul(__ldg(&g_tw[jp]), O2));

            const float2 t2 = __ldg(&g_tw[2 * j]);
            const float2 tp = make_float2(t2.x, -t2.y);
            const float2 tpn = make_float2(-t2.x, -t2.y);

            float2 S1 = make_float2(Xa.x + Xb.x, Xa.y - Xb.y);
            float2 D1 = make_float2(Xa.x - Xb.x, Xa.y + Xb.y);
            float2 zt = jmul(cmul(tp, D1));
            float2 zj = make_float2(0.5f * (S1.x + zt.x), 0.5f * (S1.y + zt.y));
            U[PADI(j)] = make_float2(zj.x, -zj.y);

            float2 S2 = make_float2(Xb.x + Xa.x, Xb.y - Xa.y);
            float2 D2 = make_float2(Xb.x - Xa.x, Xb.y + Xa.y);
            float2 zt2 = jmul(cmul(tpn, D2));
            float2 zp = make_float2(0.5f * (S2.x + zt2.x), 0.5f * (S2.y + zt2.y));
            U[PADI(jp)] = make_float2(zp.x, -zp.y);
        }
    }
    __syncthreads();

    // 256-pt forward FFT of conj(z): 3 radix-4 stages + final stage fused to gmem
    step4<256, 1>(U, V, t);  __syncthreads();
    step4<64, 4>(V, U, t);   __syncthreads();
    step4<16, 16>(U, V, t);  __syncthreads();

    // final radix-4 stage (N=4, S=64, p=0, q=t): outputs m = t + 64r, straight to gmem
    if (valid) {
        float2 a = V[PADI(t)];
        float2 b = V[PADI(t + 64)];
        float2 c = V[PADI(t + 128)];
        float2 d = V[PADI(t + 192)];
        float2 apc = cadd(a, c), amc = csub(a, c);
        float2 bpd = cadd(b, d), jbmd = jmul(csub(b, d));
        float2 Y[4];
        Y[0] = cadd(apc, bpd);
        Y[1] = csub(amc, jbmd);
        Y[2] = csub(apc, bpd);
        Y[3] = cadd(amc, jbmd);
        #pragma unroll
        for (int r = 0; r < 4; r++) {
            const int m = t + 64 * r;
            float2 o;
            o.x = Y[r].x * (1.0f / 256.0f) * g_w512[2 * m];
            o.y = -Y[r].y * (1.0f / 256.0f) * g_w512[2 * m + 1];
            *(float2*)(g_ybuf + frame * 512 + 2 * m) = o;
        }
    }
}

// ---------------- K5: OLA, 2 samples/thread ----------------
__device__ __forceinline__ float ola_generic(int s) {
    int tlo = (s >= 512) ? (s - 511 + 239) / 240 : 0;
    int thi = s / 240;
    if (thi > NFRAMES) thi = NFRAMES;
    float sig = 0.0f, env = 0.0f;
    for (int t = tlo; t <= thi; t++) {
        const int m = s - 240 * t;
        const float w = g_w512[m];
        sig += g_ybuf[t * 512 + m];
        env += w * w;
    }
    return (env > 1e-11f) ? (sig / env) : 0.0f;
}

__global__ void __launch_bounds__(256) k_ola(float* __restrict__ out) {
    const int idx = blockIdx.x * blockDim.x + threadIdx.x;
    const int n0 = idx * 2;
    if (n0 >= OUTLEN) return;
    const int s = n0 + 256;

    if (s >= 512 && s <= 3932158) {
        const int thi = s / 240;
        const int r0 = s - 240 * thi;
        const float2 v0 = *(const float2*)(g_ybuf + thi * 512 + r0);
        const float2 v1 = *(const float2*)(g_ybuf + (thi - 1) * 512 + r0 + 240);
        float sig1 = v0.x + v1.x;
        float sig2 = v0.y + v1.y;
        if (r0 <= 30) {
            const float2 v2 = *(const float2*)(g_ybuf + (thi - 2) * 512 + r0 + 480);
            sig1 += v2.x;
            sig2 += v2.y;
        }
        float2 o;
        o.x = sig1 * g_ienv[r0];
        o.y = sig2 * g_ienv[r0 + 1];
        *(float2*)(out + n0) = o;
    } else {
        out[n0] = ola_generic(s);
        if (n0 + 1 < OUTLEN) out[n0 + 1] = ola_generic(s + 1);
    }
}

// ---------------- launcher ----------------
extern "C" void kernel_launch(void* const* d_in, const int* in_sizes, int n_in,
                              void* d_out, int out_size) {
    const float* f0    = (const float*)d_in[0];
    const float* py48  = (const float*)d_in[1];
    const float* py144 = (const float*)d_in[2];
    const float* py432 = (const float*)d_in[3];
    float* out = (float*)d_out;
    (void)in_sizes; (void)n_in; (void)out_size;

    k_init<<<(LEN432 + 255) / 256, 256>>>(f0, py48, py144, py432);
    k_scan1<<<NCHUNK, CHUNKSZ>>>();
    k_scan2<<<1, NCHUNK>>>();
    k_gen<<<L2X / 4 / 256, 256>>>();
    k_fft<<<(NSTFT + FPB - 1) / FPB, 64 * FPB>>>();
    k_ola<<<(OUTLEN / 2 + 255) / 256, 256>>>(out);
}

// round 12
// speedup vs baseline: 1.1035x; 1.0326x over previous
#include <cuda_runtime.h>
#include <math.h>

#define NFRAMES   16384
#define HOPC      240
#define HOP2XC    480
#define L2X       (NFRAMES*HOP2XC)      /* 7,864,320 */
#define NSTFT     (NFRAMES+1)           /* 16385 */
#define OUTLEN    (NFRAMES*HOPC)        /* 3,932,160 */
#define PI_D      3.14159265358979323846

#define LEN48   (48*1024+1)
#define LEN144  (144*1024+1)
#define LEN432  (432*1024+1)

#define NCHUNK  128
#define CHUNKSZ 128

// ---------------- static device scratch ----------------
__device__ float  g_p2x[L2X];
__device__ float  g_ybuf[NSTFT * 512];
__device__ double g_S[NFRAMES];
__device__ double g_ex[NFRAMES];
__device__ double g_csum[NCHUNK];
__device__ double g_cbase[NCHUNK];
__device__ double g_c1[NFRAMES];
__device__ double g_c2h[NFRAMES];
__device__ float  g_af[NFRAMES];
__device__ float  g_bf[NFRAMES];
__device__ unsigned char g_vuv[NFRAMES + 1];
__device__ float  g_w1024[1024];
__device__ float  g_w512[512];
__device__ float  g_ienv[240];
__device__ float2 g_tw[1024];                 // exp(-2*pi*i*k/1024)
__device__ float  g_trans[HOP2XC];
__device__ float2 g_pr48[LEN48];
__device__ float2 g_pr144[LEN144];
__device__ float2 g_pr432[LEN432];

// ---------------- helpers ----------------
__device__ __forceinline__ float2 cmul(float2 a, float2 b) {
    return make_float2(a.x * b.x - a.y * b.y, a.x * b.y + a.y * b.x);
}
__device__ __forceinline__ float2 cadd(float2 a, float2 b) { return make_float2(a.x + b.x, a.y + b.y); }
__device__ __forceinline__ float2 csub(float2 a, float2 b) { return make_float2(a.x - b.x, a.y - b.y); }
__device__ __forceinline__ float2 jmul(float2 a) { return make_float2(-a.y, a.x); }   // i*a

#define PADI(i) ((i) + ((i) >> 3))
#define PADSZ   (512 + 64)

__device__ __forceinline__ float hannf512(int n) {
    return (float)(0.5 - 0.5 * cos(2.0 * PI_D * (double)n / 512.0));
}

__device__ __forceinline__ double block128_incl_scan(double s, double* warpsum) {
    const int t = threadIdx.x;
    const int lane = t & 31;
    const int wid = t >> 5;
    double v = s;
    #pragma unroll
    for (int off = 1; off < 32; off <<= 1) {
        double n = __shfl_up_sync(0xffffffffu, v, off);
        if (lane >= off) v += n;
    }
    if (lane == 31) warpsum[wid] = v;
    __syncthreads();
    if (t == 0) {
        double acc = 0.0;
        #pragma unroll
        for (int w = 0; w < 4; w++) { double x = warpsum[w]; warpsum[w] = acc; acc += x; }
    }
    __syncthreads();
    return v + warpsum[wid];
}

// ---------------- K-init (fp64 trig spread 1-per-432 threads across all blocks) -------
__global__ void k_init(const float* __restrict__ f0,
                       const float* __restrict__ py48, const float* __restrict__ py144,
                       const float* __restrict__ py432) {
    int i = blockIdx.x * blockDim.x + threadIdx.x;
    if (i < LEN48)  g_pr48[i]  = make_float2(py48[i],  py48[min(i + 1, LEN48 - 1)]);
    if (i < LEN144) g_pr144[i] = make_float2(py144[i], py144[min(i + 1, LEN144 - 1)]);
    if (i < LEN432) g_pr432[i] = make_float2(py432[i], py432[min(i + 1, LEN432 - 1)]);
    // spread 1024 fp64-trig items across the whole grid: k = i/432 when i%432==0
    if ((i % 432) == 0) {
        int k = i / 432;
        if (k < 1024) {
            g_w1024[k] = (float)(0.5 - 0.5 * cos(2.0 * PI_D * (double)k / 1024.0));
            double ang = -2.0 * PI_D * (double)k / 1024.0;
            g_tw[k] = make_float2((float)cos(ang), (float)sin(ang));
            if (k < 512) g_w512[k] = hannf512(k);
            if (k < HOP2XC) {
                double s = sin(((double)k / (double)HOP2XC) * (PI_D * 0.5));
                g_trans[k] = (float)(s * s);
            }
            if (k < 240) {
                float w0 = hannf512(k), w1 = hannf512(k + 240);
                float env = ((k <= 31) ? hannf512(k + 480) * hannf512(k + 480) : 0.0f)
                            + w1 * w1 + w0 * w0;
                g_ienv[k] = 1.0f / env;
            }
        }
    }
    if (i < NFRAMES) {
        double fi = (double)f0[i];
        double fn = (i + 1 < NFRAMES) ? (double)f0[i + 1] : 0.0;
        double a = (fi != 0.0) ? fi : fn;
        double b = (fn != 0.0) ? fn : fi;
        g_af[i] = (float)a;
        g_bf[i] = (float)b;
        g_c1[i] = a / 96000.0;
        g_c2h[i] = (b - a) / (2.0 * 480.0 * 96000.0);
        g_S[i] = (480.0 * a + (b - a) * (114960.0 / 480.0)) / 96000.0;
        unsigned char m = 0;
        if (fi >= 500.0 && fi < 1500.0) m |= 1;
        if (fi >= (24000.0 / 144.0) && fi < 500.0) m |= 2;
        if (fi >= (24000.0 / 432.0) && fi < (24000.0 / 144.0)) m |= 4;
        g_vuv[i] = m;
        if (i == NFRAMES - 1) g_vuv[NFRAMES] = 0;
    }
}

// ---------------- K2a/b: distributed frame scan ----------------
__global__ void __launch_bounds__(CHUNKSZ) k_scan1() {
    __shared__ double warpsum[4];
    const int i = blockIdx.x * CHUNKSZ + threadIdx.x;
    const double s = g_S[i];
    const double v = block128_incl_scan(s, warpsum);
    g_ex[i] = v - s;
    if (threadIdx.x == CHUNKSZ - 1) g_csum[blockIdx.x] = v;
}

__global__ void __launch_bounds__(NCHUNK) k_scan2() {
    __shared__ double warpsum[4];
    const double s = g_csum[threadIdx.x];
    const double v = block128_incl_scan(s, warpsum);
    g_cbase[threadIdx.x] = v - s;
}

// ---------------- K3: excitation (full fp64 phase; at L1tex gather floor) -------------
__device__ __forceinline__ float band_lookup(const float2* __restrict__ pair, int maxi,
                                             float phase, float tr, float v0, float v1) {
    if (v0 == 0.0f && v1 == 0.0f) return 0.0f;
    float mask = v0 + (v1 - v0) * tr;
    float idxf = phase * (float)maxi;
    idxf = fminf(fmaxf(idxf, 0.0f), (float)maxi);
    int lo = (int)floorf(idxf);
    float tt = idxf - (float)lo;
    float2 p = __ldg(pair + lo);
    return mask * (p.x + (p.y - p.x) * tt);
}

__global__ void __launch_bounds__(256) k_gen() {
    const int t = blockIdx.x * blockDim.x + threadIdx.x;
    const int s0 = t * 4;
    const int i = s0 / 480;
    const int j0 = s0 - i * 480;

    const double base0 = g_cbase[i >> 7] + g_ex[i];
    const double base = base0 - floor(base0);
    const double c1 = g_c1[i], c2h = g_c2h[i];
    const float af = g_af[i], bf = g_bf[i];
    const unsigned vi = g_vuv[i], vn = g_vuv[i + 1];
    const float v48a = (float)(vi & 1),         v48b = (float)(vn & 1);
    const float v144a = (float)((vi >> 1) & 1), v144b = (float)((vn >> 1) & 1);
    const float v432a = (float)((vi >> 2) & 1), v432b = (float)((vn >> 2) & 1);

    float ph[4], trv[4], f0cv[4];
    #pragma unroll
    for (int r = 0; r < 4; r++) {
        const double jd = (double)(j0 + r);
        const double u = base + (jd + 1.0) * c1 + (jd * (jd + 1.0)) * c2h;
        ph[r] = (float)(u - floor(u));
        trv[r] = g_trans[j0 + r];
        f0cv[r] = af + (bf - af) * ((float)(j0 + r) * (1.0f / 480.0f));
    }

    float4 out;
    float* op = (float*)&out;
    #pragma unroll
    for (int r = 0; r < 4; r++) {
        float acc = 0.0f;
        acc += band_lookup(g_pr48, 48 * 1024, ph[r], trv[r], v48a, v48b);
        acc += band_lookup(g_pr144, 144 * 1024, ph[r], trv[r], v144a, v144b);
        acc += band_lookup(g_pr432, 432 * 1024, ph[r], trv[r], v432a, v432b);
        op[r] = acc * f0cv[r] * (1.0f / 48000.0f);
    }
    *(float4*)(g_p2x + s0) = out;
}

// ---------------- K4: fused-load FFT512 (8·8·8) + packed IFFT256 (4·8·8, fused store) -
__device__ __forceinline__ void dft8(const float2 x[8], float2 Y[8]) {
    float2 ea = cadd(x[0], x[4]), eb = csub(x[0], x[4]);
    float2 ec = cadd(x[2], x[6]), ed = csub(x[2], x[6]);
    float2 E0 = cadd(ea, ec), E2 = csub(ea, ec);
    float2 E1 = csub(eb, jmul(ed)), E3 = cadd(eb, jmul(ed));

    float2 oa = cadd(x[1], x[5]), ob = csub(x[1], x[5]);
    float2 oc = cadd(x[3], x[7]), od = csub(x[3], x[7]);
    float2 O0 = cadd(oa, oc), O2 = csub(oa, oc);
    float2 O1 = csub(ob, jmul(od)), O3 = cadd(ob, jmul(od));

    const float C = 0.70710678118654752440f;
    float2 T1 = make_float2(C * (O1.x + O1.y), C * (O1.y - O1.x));
    float2 T2 = make_float2(O2.y, -O2.x);
    float2 T3 = make_float2(C * (O3.y - O3.x), -C * (O3.x + O3.y));

    Y[0] = cadd(E0, O0); Y[4] = csub(E0, O0);
    Y[1] = cadd(E1, T1); Y[5] = csub(E1, T1);
    Y[2] = cadd(E2, T2); Y[6] = csub(E2, T2);
    Y[3] = cadd(E3, T3); Y[7] = csub(E3, T3);
}

__device__ __forceinline__ void twiddle_store8(float2* __restrict__ dst, const float2 Y[8],
                                               int p, int q, int S, int M) {
    if (p == 0) {
        #pragma unroll
        for (int r = 0; r < 8; r++) dst[PADI(q + S * r)] = Y[r];
    } else {
        const float2 w1 = __ldg(&g_tw[p * M]);
        const float2 w2 = cmul(w1, w1);
        const float2 w3 = cmul(w2, w1);
        const float2 w4 = cmul(w2, w2);
        const float2 w5 = cmul(w4, w1);
        const float2 w6 = cmul(w4, w2);
        const float2 w7 = cmul(w4, w3);
        dst[PADI(q + S * (8 * p + 0))] = Y[0];
        dst[PADI(q + S * (8 * p + 1))] = cmul(w1, Y[1]);
        dst[PADI(q + S * (8 * p + 2))] = cmul(w2, Y[2]);
        dst[PADI(q + S * (8 * p + 3))] = cmul(w3, Y[3]);
        dst[PADI(q + S * (8 * p + 4))] = cmul(w4, Y[4]);
        dst[PADI(q + S * (8 * p + 5))] = cmul(w5, Y[5]);
        dst[PADI(q + S * (8 * p + 6))] = cmul(w6, Y[6]);
        dst[PADI(q + S * (8 * p + 7))] = cmul(w7, Y[7]);
    }
}

template<int N, int S>
__device__ __forceinline__ void step8(const float2* __restrict__ src, float2* __restrict__ dst,
                                      int t) {
    constexpr int N1 = N / 8;
    constexpr int M = 1024 / N;
    const int p = t / S;
    const int q = t - p * S;
    float2 x[8], Y[8];
    #pragma unroll
    for (int r = 0; r < 8; r++) x[r] = src[PADI(q + S * (p + r * N1))];
    dft8(x, Y);
    twiddle_store8(dst, Y, p, q, S, M);
}

template<int N, int S>
__device__ __forceinline__ void step4(const float2* __restrict__ src, float2* __restrict__ dst,
                                      int t) {
    constexpr int N1 = N / 4;
    constexpr int M = 1024 / N;
    const int p = t / S;
    const int q = t - p * S;
    float2 a = src[PADI(q + S * p)];
    float2 b = src[PADI(q + S * (p + N1))];
    float2 c = src[PADI(q + S * (p + 2 * N1))];
    float2 d = src[PADI(q + S * (p + 3 * N1))];
    float2 apc = cadd(a, c), amc = csub(a, c);
    float2 bpd = cadd(b, d), jbmd = jmul(csub(b, d));
    float2 Y0 = cadd(apc, bpd);
    float2 Y1 = csub(amc, jbmd);
    float2 Y2 = csub(apc, bpd);
    float2 Y3 = cadd(amc, jbmd);
    const float2 w1 = __ldg(&g_tw[p * M]);
    const float2 w2 = cmul(w1, w1);
    const float2 w3 = cmul(w2, w1);
    dst[PADI(q + S * (4 * p + 0))] = Y0;
    dst[PADI(q + S * (4 * p + 1))] = cmul(w1, Y1);
    dst[PADI(q + S * (4 * p + 2))] = cmul(w2, Y2);
    dst[PADI(q + S * (4 * p + 3))] = cmul(w3, Y3);
}

#define FPB 4

__global__ void __launch_bounds__(64 * FPB) k_fft() {
    __shared__ float2 Ub[FPB][PADSZ];
    __shared__ float2 Vb[FPB][PADSZ];
    const int tid = threadIdx.x;
    const int sub = tid >> 6;
    const int t = tid & 63;
    const int frame = blockIdx.x * FPB + sub;
    const bool valid = (frame < NSTFT);

    float2* U = Ub[sub];
    float2* V = Vb[sub];

    // ---- fused: gmem load + window + pack + first radix-8 stage (S=1, p=t, q=0) ----
    {
        float2 x[8], Y[8];
        #pragma unroll
        for (int r = 0; r < 8; r++) {
            const int n0 = t + 64 * r;
            float xe = 0.0f, xo = 0.0f;
            if (valid) {
                int ge = frame * HOP2XC - 512 + 2 * n0;
                if (ge >= 0 && ge + 1 < L2X) {
                    float2 v = *(const float2*)(g_p2x + ge);
                    xe = v.x; xo = v.y;
                } else {
                    int go = ge + 1;
                    if (ge < 0) ge = -ge;
                    if (ge >= L2X) ge = 2 * L2X - 2 - ge;
                    if (go < 0) go = -go;
                    if (go >= L2X) go = 2 * L2X - 2 - go;
                    xe = g_p2x[ge];
                    xo = g_p2x[go];
                }
                xe *= g_w1024[2 * n0];
                xo *= g_w1024[2 * n0 + 1];
            }
            x[r] = make_float2(xe, xo);
        }
        dft8(x, Y);
        twiddle_store8(V, Y, t, 0, 1, 2);     // N=512: S=1, M=2
    }
    __syncthreads();

    step8<64, 8>(V, U, t);   __syncthreads();
    step8<8, 64>(U, V, t);   __syncthreads();

    // unpack real-FFT bins X[0..256], build conj of irfft-256 packing in U[0..255]
    for (int j = t; j <= 128; j += 64) {
        const float2 Zj = V[PADI(j)];
        const float2 Zmj = V[PADI((512 - j) & 511)];
        float2 E = make_float2(0.5f * (Zj.x + Zmj.x), 0.5f * (Zj.y - Zmj.y));
        float2 O = make_float2(0.5f * (Zj.y + Zmj.y), -0.5f * (Zj.x - Zmj.x));
        float2 Xa = cadd(E, cmul(__ldg(&g_tw[j]), O));
        if (j == 0) {
            const float X0r = Xa.x;
            const float X256r = V[PADI(256)].x;
            U[PADI(0)] = make_float2(0.5f * (X0r + X256r), -0.5f * (X0r - X256r));
        } else {
            const int jp = 256 - j;
            const float2 Zk = V[PADI(jp)];
            const float2 Zmk = V[PADI(256 + j)];
            float2 E2 = make_float2(0.5f * (Zk.x + Zmk.x), 0.5f * (Zk.y - Zmk.y));
            float2 O2 = make_float2(0.5f * (Zk.y + Zmk.y), -0.5f * (Zk.x - Zmk.x));
            float2 Xb = cadd(E2, cmul(__ldg(&g_tw[jp]), O2));

            const float2 t2 = __ldg(&g_tw[2 * j]);
            const float2 tp = make_float2(t2.x, -t2.y);
            const float2 tpn = make_float2(-t2.x, -t2.y);

            float2 S1 = make_float2(Xa.x + Xb.x, Xa.y - Xb.y);
            float2 D1 = make_float2(Xa.x - Xb.x, Xa.y + Xb.y);
            float2 zt = jmul(cmul(tp, D1));
            float2 zj = make_float2(0.5f * (S1.x + zt.x), 0.5f * (S1.y + zt.y));
            U[PADI(j)] = make_float2(zj.x, -zj.y);

            float2 S2 = make_float2(Xb.x + Xa.x, Xb.y - Xa.y);
            float2 D2 = make_float2(Xb.x - Xa.x, Xb.y + Xa.y);
            float2 zt2 = jmul(cmul(tpn, D2));
            float2 zp = make_float2(0.5f * (S2.x + zt2.x), 0.5f * (S2.y + zt2.y));
            U[PADI(jp)] = make_float2(zp.x, -zp.y);
        }
    }
    __syncthreads();

    // 256-pt forward FFT of conj(z) as 4·8·8: two smem stages + fused-store final
    step4<256, 1>(U, V, t);  __syncthreads();
    if (t < 32) step8<64, 4>(V, U, t);
    __syncthreads();

    // final radix-8 (N=8, S=32, p=0): 32 threads, outputs m = t + 32r, straight to gmem
    if (valid && t < 32) {
        float2 x[8], Y[8];
        #pragma unroll
        for (int r = 0; r < 8; r++) x[r] = U[PADI(t + 32 * r)];
        dft8(x, Y);
        #pragma unroll
        for (int r = 0; r < 8; r++) {
            const int m = t + 32 * r;
            float2 o;
            o.x = Y[r].x * (1.0f / 256.0f) * g_w512[2 * m];
            o.y = -Y[r].y * (1.0f / 256.0f) * g_w512[2 * m + 1];
            *(float2*)(g_ybuf + frame * 512 + 2 * m) = o;
        }
    }
}

// ---------------- K5: OLA, 4 samples/thread, float4 ----------------
__device__ __forceinline__ float ola_generic(int s) {
    int tlo = (s >= 512) ? (s - 511 + 239) / 240 : 0;
    int thi = s / 240;
    if (thi > NFRAMES) thi = NFRAMES;
    float sig = 0.0f, env = 0.0f;
    for (int t = tlo; t <= thi; t++) {
        const int m = s - 240 * t;
        const float w = g_w512[m];
        sig += g_ybuf[t * 512 + m];
        env += w * w;
    }
    return (env > 1e-11f) ? (sig / env) : 0.0f;
}

__global__ void __launch_bounds__(256) k_ola(float* __restrict__ out) {
    const int idx = blockIdx.x * blockDim.x + threadIdx.x;   // OUTLEN/4 threads
    const int n0 = idx * 4;
    if (n0 >= OUTLEN) return;
    const int s = n0 + 256;                                   // s % 4 == 0

    if (s >= 512 && s <= 16384 * 240 + 236) {
        // interior: all 4 samples share the same frame-term set; r0 % 4 == 0
        const int thi = s / 240;
        const int r0 = s - 240 * thi;                         // 0..236, mult of 4
        const float4 v0 = *(const float4*)(g_ybuf + thi * 512 + r0);
        const float4 v1 = *(const float4*)(g_ybuf + (thi - 1) * 512 + r0 + 240);
        float4 sig = make_float4(v0.x + v1.x, v0.y + v1.y, v0.z + v1.z, v0.w + v1.w);
        if (r0 <= 28) {
            const float4 v2 = *(const float4*)(g_ybuf + (thi - 2) * 512 + r0 + 480);
            sig.x += v2.x; sig.y += v2.y; sig.z += v2.z; sig.w += v2.w;
        }
        const float4 ie = *(const float4*)(g_ienv + r0);
        float4 o;
        o.x = sig.x * ie.x;
        o.y = sig.y * ie.y;
        o.z = sig.z * ie.z;
        o.w = sig.w * ie.w;
        *(float4*)(out + n0) = o;
    } else {
        #pragma unroll
        for (int k = 0; k < 4; k++)
            if (n0 + k < OUTLEN) out[n0 + k] = ola_generic(s + k);
    }
}

// ---------------- launcher ----------------
extern "C" void kernel_launch(void* const* d_in, const int* in_sizes, int n_in,
                              void* d_out, int out_size) {
    const float* f0    = (const float*)d_in[0];
    const float* py48  = (const float*)d_in[1];
    const float* py144 = (const float*)d_in[2];
    const float* py432 = (const float*)d_in[3];
    float* out = (float*)d_out;
    (void)in_sizes; (void)n_in; (void)out_size;

    k_init<<<(LEN432 + 255) / 256, 256>>>(f0, py48, py144, py432);
    k_scan1<<<NCHUNK, CHUNKSZ>>>();
    k_scan2<<<1, NCHUNK>>>();
    k_gen<<<L2X / 4 / 256, 256>>>();
    k_fft<<<(NSTFT + FPB - 1) / FPB, 64 * FPB>>>();
    k_ola<<<(OUTLEN / 4 + 255) / 256, 256>>>(out);
}